// round 2
// baseline (speedup 1.0000x reference)
#include <cuda_runtime.h>
#include <math.h>

#define NQ       12
#define NLAYERS  5
#define DIM      4096
#define BSZ      4096

// ---------------- device scratch (no allocations allowed) ----------------
__device__ float2 g_psi0[DIM];
__device__ float2 g_phi[(size_t)BSZ * DIM];   // 128 MB: per-sample states (re,im)

__device__ __forceinline__ float2 cmul(float2 a, float2 b) {
    return make_float2(a.x * b.x - a.y * b.y, a.x * b.y + a.y * b.x);
}
__device__ __forceinline__ float2 cadd(float2 a, float2 b) {
    return make_float2(a.x + b.x, a.y + b.y);
}

// Reference einsum 'st,blsr->bltr' applies U^T. We build T = U^T directly,
// where U = RZ(lam) @ RY(theta) @ RZ(phi):
//   U00 =  c*e^{-i(lam+phi)/2}   U01 = -s*e^{-i(lam-phi)/2}
//   U10 =  s*e^{ i(lam-phi)/2}   U11 =  c*e^{ i(lam+phi)/2}
// T = [[U00, U10], [U01, U11]]
__device__ __forceinline__ void make_UT(float ph, float th, float lm,
                                        float2& T00, float2& T01,
                                        float2& T10, float2& T11) {
    float ct = cosf(0.5f * th), st = sinf(0.5f * th);
    float ap = 0.5f * (lm + ph), am = 0.5f * (lm - ph);
    float cap = cosf(ap), sap = sinf(ap);
    float cam = cosf(am), sam = sinf(am);
    float2 U00 = make_float2( ct * cap, -ct * sap);
    float2 U01 = make_float2(-st * cam,  st * sam);
    float2 U10 = make_float2( st * cam,  st * sam);
    float2 U11 = make_float2( ct * cap,  ct * sap);
    T00 = U00; T01 = U10; T10 = U01; T11 = U11;
}

// ---------------- Kernel A: data-independent prefix (layers 0..3) --------
__global__ void k_psi0(const float* __restrict__ params) {
    __shared__ float2 st[DIM];
    int tid = threadIdx.x, nt = blockDim.x;
    for (int i = tid; i < DIM; i += nt)
        st[i] = make_float2(i == 0 ? 1.0f : 0.0f, 0.0f);
    __syncthreads();

    for (int l = 0; l < NLAYERS - 1; l++) {
        for (int q = 0; q < NQ; q++) {
            const float* p = params + (l * NQ + q) * 3;
            float2 T00, T01, T10, T11;
            make_UT(p[0], p[1], p[2], T00, T01, T10, T11);
            int mask = 1 << (NQ - 1 - q);
            for (int pi = tid; pi < DIM / 2; pi += nt) {
                int low = pi & (mask - 1);
                int hi  = (pi & ~(mask - 1)) << 1;
                int i0 = hi | low, i1 = i0 | mask;
                float2 s0 = st[i0], s1 = st[i1];
                st[i0] = cadd(cmul(T00, s0), cmul(T01, s1));
                st[i1] = cadd(cmul(T10, s0), cmul(T11, s1));
            }
            __syncthreads();
        }
        for (int q = 0; q < NQ - 1; q++) {
            int cb = 1 << (NQ - 1 - q);
            int tb = 1 << (NQ - 2 - q);
            for (int idx = tid; idx < DIM; idx += nt) {
                if ((idx & cb) && !(idx & tb)) {
                    float2 t0 = st[idx], t1 = st[idx | tb];
                    st[idx] = t1;
                    st[idx | tb] = t0;
                }
            }
            __syncthreads();
        }
    }
    for (int i = tid; i < DIM; i += nt) g_psi0[i] = st[i];
}

// ---------------- Kernel B: per-sample layer-4 product gates -------------
// Reference applies state <- G^T (U^T state) per qubit. Effective 2x2 gate:
//   V = G^T @ T,  G^T = [[gc, gs], [-gs, gc]],  T = U^T.
// The trailing CNOT chain is a fixed basis permutation -> cancels in the
// Gram matrix, dropped.
__global__ void k_states(const float* __restrict__ X,
                         const float* __restrict__ params) {
    __shared__ float2 st[DIM];
    int i = blockIdx.x, tid = threadIdx.x, nt = blockDim.x;
    for (int k = tid; k < DIM; k += nt) st[k] = g_psi0[k];
    __syncthreads();

    for (int q = 0; q < NQ; q++) {
        const float* p = params + ((NLAYERS - 1) * NQ + q) * 3;
        float2 T00, T01, T10, T11;
        make_UT(p[0], p[1], p[2], T00, T01, T10, T11);
        float x = X[i * NQ + q];
        float gc = cosf(0.5f * x), gs = sinf(0.5f * x);
        // V = G^T * T
        float2 V00 = make_float2(gc * T00.x + gs * T10.x, gc * T00.y + gs * T10.y);
        float2 V01 = make_float2(gc * T01.x + gs * T11.x, gc * T01.y + gs * T11.y);
        float2 V10 = make_float2(-gs * T00.x + gc * T10.x, -gs * T00.y + gc * T10.y);
        float2 V11 = make_float2(-gs * T01.x + gc * T11.x, -gs * T01.y + gc * T11.y);

        int mask = 1 << (NQ - 1 - q);
        for (int pi = tid; pi < DIM / 2; pi += nt) {
            int low = pi & (mask - 1);
            int hi  = (pi & ~(mask - 1)) << 1;
            int i0 = hi | low, i1 = i0 | mask;
            float2 s0 = st[i0], s1 = st[i1];
            st[i0] = cadd(cmul(V00, s0), cmul(V01, s1));
            st[i1] = cadd(cmul(V10, s0), cmul(V11, s1));
        }
        __syncthreads();
    }
    for (int k = tid; k < DIM; k += nt)
        g_phi[(size_t)i * DIM + k] = st[k];
}

// ---------------- Kernel C: K = |Phi Phi^H|^2, upper-triangular tiles ----
#define BM 128
#define BK 8
#define NTILE (DIM / BM)                      // 32
#define NBLK  (NTILE * (NTILE + 1) / 2)       // 528

__global__ __launch_bounds__(256, 1) void k_gram(float* __restrict__ K) {
    __shared__ float2 As[BK][BM + 1];
    __shared__ float2 Bs[BK][BM + 1];

    int t = blockIdx.x;
    int bj = (int)((sqrtf(8.0f * (float)t + 1.0f) - 1.0f) * 0.5f);
    while ((bj + 1) * (bj + 2) / 2 <= t) bj++;
    while (bj * (bj + 1) / 2 > t) bj--;
    int bi = t - bj * (bj + 1) / 2;           // bi <= bj

    int rowbase = bi * BM;                    // i-tile
    int colbase = bj * BM;                    // j-tile
    int tid = threadIdx.x;
    int tx = tid & 15, ty = tid >> 4;

    float acc_re[8][8], acc_im[8][8];
#pragma unroll
    for (int n = 0; n < 8; n++)
#pragma unroll
        for (int m = 0; m < 8; m++) { acc_re[n][m] = 0.f; acc_im[n][m] = 0.f; }

    // global-load mapping: 256 threads x (4 rows each) cover 128 rows x 8 k
    int lk = tid & 7;
    int lm = tid >> 3;                        // 0..31, +32*r
    const float2* Abase = g_phi + (size_t)rowbase * DIM;
    const float2* Bbase = g_phi + (size_t)colbase * DIM;

    float2 ra[4], rb[4];
#pragma unroll
    for (int r = 0; r < 4; r++) {
        ra[r] = Abase[(size_t)(lm + 32 * r) * DIM + lk];
        rb[r] = Bbase[(size_t)(lm + 32 * r) * DIM + lk];
    }

    for (int kt = 0; kt < DIM / BK; kt++) {
        __syncthreads();
#pragma unroll
        for (int r = 0; r < 4; r++) {
            As[lk][lm + 32 * r] = ra[r];
            Bs[lk][lm + 32 * r] = rb[r];
        }
        __syncthreads();

        if (kt + 1 < DIM / BK) {              // prefetch next k-tile
            int k0 = (kt + 1) * BK + lk;
#pragma unroll
            for (int r = 0; r < 4; r++) {
                ra[r] = Abase[(size_t)(lm + 32 * r) * DIM + k0];
                rb[r] = Bbase[(size_t)(lm + 32 * r) * DIM + k0];
            }
        }

#pragma unroll
        for (int kk = 0; kk < BK; kk++) {
            float2 a[8], b[8];
#pragma unroll
            for (int n = 0; n < 8; n++) a[n] = As[kk][ty + 16 * n];
#pragma unroll
            for (int m = 0; m < 8; m++) b[m] = Bs[kk][tx + 16 * m];
#pragma unroll
            for (int n = 0; n < 8; n++)
#pragma unroll
                for (int m = 0; m < 8; m++) {
                    // g_ij = sum_k phi_ik * conj(phi_jk)
                    acc_re[n][m] += a[n].x * b[m].x + a[n].y * b[m].y;
                    acc_im[n][m] += a[n].y * b[m].x - a[n].x * b[m].y;
                }
        }
    }

#pragma unroll
    for (int n = 0; n < 8; n++) {
        int row = rowbase + ty + 16 * n;
#pragma unroll
        for (int m = 0; m < 8; m++) {
            int col = colbase + tx + 16 * m;
            float re = acc_re[n][m], im = acc_im[n][m];
            float v = re * re + im * im;
            K[(size_t)row * BSZ + col] = v;
            if (bi != bj) K[(size_t)col * BSZ + row] = v;
        }
    }
}

// -------------------------------------------------------------------------
extern "C" void kernel_launch(void* const* d_in, const int* in_sizes, int n_in,
                              void* d_out, int out_size) {
    const float* X      = (const float*)d_in[0];   // (4096, 12)
    const float* params = (const float*)d_in[1];   // (5, 12, 3)
    float* K = (float*)d_out;                      // (4096, 4096)

    k_psi0  <<<1,   256>>>(params);
    k_states<<<BSZ, 256>>>(X, params);
    k_gram  <<<NBLK, 256>>>(K);
}

// round 4
// speedup vs baseline: 3.8011x; 3.8011x over previous
#include <cuda_runtime.h>
#include <cuda_bf16.h>
#include <math.h>
#include <cstdint>

#define NQ       12
#define NLAYERS  5
#define DIM      4096
#define BSZ      4096

// ---------------- device scratch (no allocations allowed) ----------------
__device__ float2 g_psi0[DIM];
// bf16 split operands, K interleaved (re,im) per complex element:
//   A = [re, im],  hi + lo split.  (imag-operand C = [-im, re] is derived
//   in-register in the GEMM from the same fragments.)
__device__ __align__(128) __nv_bfloat162 g_Ah[(size_t)BSZ * DIM];
__device__ __align__(128) __nv_bfloat162 g_Al[(size_t)BSZ * DIM];

__device__ __forceinline__ float2 cmul(float2 a, float2 b) {
    return make_float2(a.x * b.x - a.y * b.y, a.x * b.y + a.y * b.x);
}
__device__ __forceinline__ float2 cadd(float2 a, float2 b) {
    return make_float2(a.x + b.x, a.y + b.y);
}

// Reference einsum 'st,blsr->bltr' applies U^T. T = U^T.
__device__ __forceinline__ void make_UT(float ph, float th, float lm,
                                        float2& T00, float2& T01,
                                        float2& T10, float2& T11) {
    float ct = cosf(0.5f * th), st = sinf(0.5f * th);
    float ap = 0.5f * (lm + ph), am = 0.5f * (lm - ph);
    float cap = cosf(ap), sap = sinf(ap);
    float cam = cosf(am), sam = sinf(am);
    float2 U00 = make_float2( ct * cap, -ct * sap);
    float2 U01 = make_float2(-st * cam,  st * sam);
    float2 U10 = make_float2( st * cam,  st * sam);
    float2 U11 = make_float2( ct * cap,  ct * sap);
    T00 = U00; T01 = U10; T10 = U01; T11 = U11;
}

// ---------------- Kernel A: data-independent prefix (layers 0..3) --------
__global__ void k_psi0(const float* __restrict__ params) {
    __shared__ float2 st[DIM];
    int tid = threadIdx.x, nt = blockDim.x;
    for (int i = tid; i < DIM; i += nt)
        st[i] = make_float2(i == 0 ? 1.0f : 0.0f, 0.0f);
    __syncthreads();

    for (int l = 0; l < NLAYERS - 1; l++) {
        for (int q = 0; q < NQ; q++) {
            const float* p = params + (l * NQ + q) * 3;
            float2 T00, T01, T10, T11;
            make_UT(p[0], p[1], p[2], T00, T01, T10, T11);
            int mask = 1 << (NQ - 1 - q);
            for (int pi = tid; pi < DIM / 2; pi += nt) {
                int low = pi & (mask - 1);
                int hi  = (pi & ~(mask - 1)) << 1;
                int i0 = hi | low, i1 = i0 | mask;
                float2 s0 = st[i0], s1 = st[i1];
                st[i0] = cadd(cmul(T00, s0), cmul(T01, s1));
                st[i1] = cadd(cmul(T10, s0), cmul(T11, s1));
            }
            __syncthreads();
        }
        for (int q = 0; q < NQ - 1; q++) {
            int cb = 1 << (NQ - 1 - q);
            int tb = 1 << (NQ - 2 - q);
            for (int idx = tid; idx < DIM; idx += nt) {
                if ((idx & cb) && !(idx & tb)) {
                    float2 t0 = st[idx], t1 = st[idx | tb];
                    st[idx] = t1;
                    st[idx | tb] = t0;
                }
            }
            __syncthreads();
        }
    }
    for (int i = tid; i < DIM; i += nt) g_psi0[i] = st[i];
}

// ---------------- Kernel B: per-sample layer-4 gates + bf16 split --------
__global__ void k_states(const float* __restrict__ X,
                         const float* __restrict__ params) {
    __shared__ float2 st[DIM];
    int i = blockIdx.x, tid = threadIdx.x, nt = blockDim.x;
    for (int k = tid; k < DIM; k += nt) st[k] = g_psi0[k];
    __syncthreads();

    for (int q = 0; q < NQ; q++) {
        const float* p = params + ((NLAYERS - 1) * NQ + q) * 3;
        float2 T00, T01, T10, T11;
        make_UT(p[0], p[1], p[2], T00, T01, T10, T11);
        float x = X[i * NQ + q];
        float gc = cosf(0.5f * x), gs = sinf(0.5f * x);
        // V = G^T * T
        float2 V00 = make_float2(gc * T00.x + gs * T10.x, gc * T00.y + gs * T10.y);
        float2 V01 = make_float2(gc * T01.x + gs * T11.x, gc * T01.y + gs * T11.y);
        float2 V10 = make_float2(-gs * T00.x + gc * T10.x, -gs * T00.y + gc * T10.y);
        float2 V11 = make_float2(-gs * T01.x + gc * T11.x, -gs * T01.y + gc * T11.y);

        int mask = 1 << (NQ - 1 - q);
        for (int pi = tid; pi < DIM / 2; pi += nt) {
            int low = pi & (mask - 1);
            int hi  = (pi & ~(mask - 1)) << 1;
            int i0 = hi | low, i1 = i0 | mask;
            float2 s0 = st[i0], s1 = st[i1];
            st[i0] = cadd(cmul(V00, s0), cmul(V01, s1));
            st[i1] = cadd(cmul(V10, s0), cmul(V11, s1));
        }
        __syncthreads();
    }

    size_t rowoff = (size_t)i * DIM;
    for (int k = tid; k < DIM; k += nt) {
        float re = st[k].x, im = st[k].y;
        __nv_bfloat16 hr = __float2bfloat16_rn(re);
        __nv_bfloat16 hi = __float2bfloat16_rn(im);
        __nv_bfloat16 lr = __float2bfloat16_rn(re - __bfloat162float(hr));
        __nv_bfloat16 li = __float2bfloat16_rn(im - __bfloat162float(hi));
        __nv_bfloat162 ah; ah.x = hr; ah.y = hi;
        __nv_bfloat162 al; al.x = lr; al.y = li;
        g_Ah[rowoff + k] = ah;
        g_Al[rowoff + k] = al;
    }
}

// =============  Kernel C: HMMA (mma.sync bf16) split Gram  ================
// g_re = A.A^T, g_im = A.C^T over interleaved K=8192 bf16, split hi/lo:
//   re: Ah.Ah + Ah.Al + Al.Ah ; im: same with B' fragments derived from B
//   (B' = halves swapped + sign flip: (re,im) -> (-im,re)).
// K_out = re^2 + im^2.  Triangular 128x128 tiles.
#define KELEMS    8192
#define KCHUNK    64                    // bf16 per chunk (128 bytes)
#define NKT       (KELEMS / KCHUNK)     // 128
#define TILE_B    16384                 // 128 rows x 128 bytes
#define STAGE_B   (4 * TILE_B)          // Ah_i, Al_i, Ah_j, Al_j = 64KB
#define NSTAGE    3
#define GRAM_SMEM (NSTAGE * STAGE_B)    // 192KB
#define GRAM_THREADS 256
#define NTILE (DIM / 128)               // 32
#define NBLK  (NTILE * (NTILE + 1) / 2) // 528

__device__ __forceinline__ uint32_t smem_u32(const void* p) {
    return (uint32_t)__cvta_generic_to_shared(p);
}
__device__ __forceinline__ void cp_async16(uint32_t dst, const void* src) {
    asm volatile("cp.async.cg.shared.global [%0], [%1], 16;" :: "r"(dst), "l"(src));
}
#define CP_COMMIT()  asm volatile("cp.async.commit_group;" ::: "memory")
#define CP_WAIT2()   asm volatile("cp.async.wait_group 2;" ::: "memory")

__device__ __forceinline__ void ldsm4(uint32_t* r, uint32_t addr) {
    asm volatile("ldmatrix.sync.aligned.m8n8.x4.shared.b16 {%0,%1,%2,%3}, [%4];"
        : "=r"(r[0]), "=r"(r[1]), "=r"(r[2]), "=r"(r[3]) : "r"(addr));
}
__device__ __forceinline__ void mma_bf16(float* c, const uint32_t* a,
                                         uint32_t b0, uint32_t b1) {
    asm volatile(
        "mma.sync.aligned.m16n8k16.row.col.f32.bf16.bf16.f32 "
        "{%0,%1,%2,%3}, {%4,%5,%6,%7}, {%8,%9}, {%0,%1,%2,%3};"
        : "+f"(c[0]), "+f"(c[1]), "+f"(c[2]), "+f"(c[3])
        : "r"(a[0]), "r"(a[1]), "r"(a[2]), "r"(a[3]), "r"(b0), "r"(b1));
}
// (re,im) packed pair -> (-im, re)
__device__ __forceinline__ uint32_t derive_c(uint32_t b) {
    return __byte_perm(b, b, 0x1032) ^ 0x00008000u;
}

__global__ void __launch_bounds__(GRAM_THREADS, 1)
k_gram_mma(float* __restrict__ K) {
    extern __shared__ __align__(1024) char smem[];
    const uint32_t smem_base = smem_u32(smem);
    const int tid  = threadIdx.x;
    const int wid  = tid >> 5;
    const int lane = tid & 31;
    const int wm = wid >> 2;            // 0..1  (64-row slab)
    const int wn = wid & 3;             // 0..3  (32-col slab)

    // triangular tile mapping (bi <= bj)
    int t = blockIdx.x;
    int bj = (int)((sqrtf(8.0f * (float)t + 1.0f) - 1.0f) * 0.5f);
    while ((bj + 1) * (bj + 2) / 2 <= t) bj++;
    while (bj * (bj + 1) / 2 > t) bj--;
    int bi = t - bj * (bj + 1) / 2;

    const char* gsrc[4];
    gsrc[0] = (const char*)g_Ah + (size_t)bi * 128 * 16384;
    gsrc[1] = (const char*)g_Al + (size_t)bi * 128 * 16384;
    gsrc[2] = (const char*)g_Ah + (size_t)bj * 128 * 16384;
    gsrc[3] = (const char*)g_Al + (size_t)bj * 128 * 16384;

    // ldmatrix per-thread geometry
    const int mat = lane >> 3, rl = lane & 7;
    const int rowA_base = wm * 64 + (mat & 1) * 8 + rl;   // + mt*16
    const uint32_t kselA = (uint32_t)((mat >> 1) * 16);
    const uint32_t xA = (uint32_t)(rowA_base & 7) << 4;
    const int rowB_base = wn * 32 + (mat >> 1) * 8 + rl;  // + np*16
    const uint32_t kselB = (uint32_t)((mat & 1) * 16);
    const uint32_t xB = (uint32_t)(rowB_base & 7) << 4;

    float acc[2][4][4][4];
#pragma unroll
    for (int e = 0; e < 2; e++)
#pragma unroll
        for (int mt = 0; mt < 4; mt++)
#pragma unroll
            for (int nt = 0; nt < 4; nt++)
#pragma unroll
                for (int r = 0; r < 4; r++) acc[e][mt][nt][r] = 0.f;

    // ---------------- prologue: fill 3 stages --------------------------
#pragma unroll 1
    for (int pk = 0; pk < NSTAGE; pk++) {
        uint32_t sb = smem_base + pk * STAGE_B;
#pragma unroll
        for (int tt = 0; tt < 4; tt++) {
#pragma unroll
            for (int u = 0; u < 4; u++) {
                int p = u * 256 + tid;
                int rr = p >> 3, cc = p & 7;
                uint32_t dst = sb + tt * TILE_B + (uint32_t)rr * 128 +
                               (((uint32_t)cc * 16) ^ (((uint32_t)rr & 7) << 4));
                cp_async16(dst, gsrc[tt] + (size_t)rr * 16384 + pk * 128 + cc * 16);
            }
        }
        CP_COMMIT();
    }

    // ---------------- main loop ----------------------------------------
#pragma unroll 1
    for (int kt = 0; kt < NKT; kt++) {
        CP_WAIT2();
        __syncthreads();

        uint32_t sb = smem_base + (kt % NSTAGE) * STAGE_B;
        uint32_t aH = sb + (uint32_t)rowA_base * 128;
        uint32_t aL = aH + TILE_B;
        uint32_t bH = sb + 2 * TILE_B + (uint32_t)rowB_base * 128;
        uint32_t bL = bH + TILE_B;

#pragma unroll
        for (int ks = 0; ks < 4; ks++) {
            uint32_t cA = ((uint32_t)(ks * 32) + kselA) ^ xA;
            uint32_t cB = ((uint32_t)(ks * 32) + kselB) ^ xB;

            uint32_t ah[4][4], al[4][4];
#pragma unroll
            for (int mt = 0; mt < 4; mt++) {
                ldsm4(ah[mt], aH + mt * 2048 + cA);
                ldsm4(al[mt], aL + mt * 2048 + cA);
            }
            uint32_t bh[2][4], bl[2][4], bhp[2][4], blp[2][4];
#pragma unroll
            for (int np = 0; np < 2; np++) {
                ldsm4(bh[np], bH + np * 2048 + cB);
                ldsm4(bl[np], bL + np * 2048 + cB);
#pragma unroll
                for (int r = 0; r < 4; r++) {
                    bhp[np][r] = derive_c(bh[np][r]);
                    blp[np][r] = derive_c(bl[np][r]);
                }
            }

#pragma unroll
            for (int mt = 0; mt < 4; mt++) {
#pragma unroll
                for (int np = 0; np < 2; np++) {
#pragma unroll
                    for (int h = 0; h < 2; h++) {
                        int nt = np * 2 + h;
                        uint32_t b0 = bh[np][h * 2], b1 = bh[np][h * 2 + 1];
                        uint32_t l0 = bl[np][h * 2], l1 = bl[np][h * 2 + 1];
                        uint32_t p0 = bhp[np][h * 2], p1 = bhp[np][h * 2 + 1];
                        uint32_t q0 = blp[np][h * 2], q1 = blp[np][h * 2 + 1];
                        mma_bf16(acc[0][mt][nt], ah[mt], b0, b1);
                        mma_bf16(acc[0][mt][nt], ah[mt], l0, l1);
                        mma_bf16(acc[0][mt][nt], al[mt], b0, b1);
                        mma_bf16(acc[1][mt][nt], ah[mt], p0, p1);
                        mma_bf16(acc[1][mt][nt], ah[mt], q0, q1);
                        mma_bf16(acc[1][mt][nt], al[mt], p0, p1);
                    }
                }
            }
        }

        __syncthreads();

        int nk = kt + NSTAGE;
        if (nk < NKT) {
#pragma unroll
            for (int tt = 0; tt < 4; tt++) {
#pragma unroll
                for (int u = 0; u < 4; u++) {
                    int p = u * 256 + tid;
                    int rr = p >> 3, cc = p & 7;
                    uint32_t dst = sb + tt * TILE_B + (uint32_t)rr * 128 +
                                   (((uint32_t)cc * 16) ^ (((uint32_t)rr & 7) << 4));
                    cp_async16(dst, gsrc[tt] + (size_t)rr * 16384 + nk * 128 + cc * 16);
                }
            }
        }
        CP_COMMIT();
    }

    // ---------------- epilogue: K = re^2 + im^2 ------------------------
    const int r0 = bi * 128 + wm * 64 + (lane >> 2);
    const int c0 = bj * 128 + wn * 32 + (lane & 3) * 2;
#pragma unroll
    for (int mt = 0; mt < 4; mt++) {
#pragma unroll
        for (int nt = 0; nt < 4; nt++) {
            int row = r0 + mt * 16;
            int col = c0 + nt * 8;
            float* re = acc[0][mt][nt];
            float* im = acc[1][mt][nt];
            float v00 = re[0] * re[0] + im[0] * im[0];
            float v01 = re[1] * re[1] + im[1] * im[1];
            float v10 = re[2] * re[2] + im[2] * im[2];
            float v11 = re[3] * re[3] + im[3] * im[3];
            *(float2*)(K + (size_t)row * BSZ + col)       = make_float2(v00, v01);
            *(float2*)(K + (size_t)(row + 8) * BSZ + col) = make_float2(v10, v11);
            if (bi != bj) {
                K[(size_t)col * BSZ + row]           = v00;
                K[(size_t)(col + 1) * BSZ + row]     = v01;
                K[(size_t)col * BSZ + row + 8]       = v10;
                K[(size_t)(col + 1) * BSZ + row + 8] = v11;
            }
        }
    }
}

// -------------------------------------------------------------------------
extern "C" void kernel_launch(void* const* d_in, const int* in_sizes, int n_in,
                              void* d_out, int out_size) {
    const float* X      = (const float*)d_in[0];   // (4096, 12)
    const float* params = (const float*)d_in[1];   // (5, 12, 3)
    float* K = (float*)d_out;                      // (4096, 4096)

    cudaFuncSetAttribute(k_gram_mma, cudaFuncAttributeMaxDynamicSharedMemorySize,
                         GRAM_SMEM);

    k_psi0    <<<1,    1024>>>(params);
    k_states  <<<BSZ,  256>>>(X, params);
    k_gram_mma<<<NBLK, GRAM_THREADS, GRAM_SMEM>>>(K);
}

// round 5
// speedup vs baseline: 5.2713x; 1.3868x over previous
#include <cuda_runtime.h>
#include <cuda_bf16.h>
#include <math.h>
#include <cstdint>

#define NQ       12
#define NLAYERS  5
#define DIM      4096
#define BSZ      4096

// ---------------- device scratch (no allocations allowed) ----------------
__device__ float2 g_psi0[DIM];
// bf16 split operands, K interleaved (re,im) per complex element:
//   A = [re, im],  hi + lo split.  (imag-operand C = [-im, re] is derived
//   in-register in the GEMM from the same fragments.)
__device__ __align__(128) __nv_bfloat162 g_Ah[(size_t)BSZ * DIM];
__device__ __align__(128) __nv_bfloat162 g_Al[(size_t)BSZ * DIM];

__device__ __forceinline__ float2 cmul(float2 a, float2 b) {
    return make_float2(a.x * b.x - a.y * b.y, a.x * b.y + a.y * b.x);
}
__device__ __forceinline__ float2 cadd(float2 a, float2 b) {
    return make_float2(a.x + b.x, a.y + b.y);
}

// Reference einsum 'st,blsr->bltr' applies U^T. T = U^T.
__device__ __forceinline__ void make_UT(float ph, float th, float lm,
                                        float2& T00, float2& T01,
                                        float2& T10, float2& T11) {
    float ct = cosf(0.5f * th), st = sinf(0.5f * th);
    float ap = 0.5f * (lm + ph), am = 0.5f * (lm - ph);
    float cap = cosf(ap), sap = sinf(ap);
    float cam = cosf(am), sam = sinf(am);
    float2 U00 = make_float2( ct * cap, -ct * sap);
    float2 U01 = make_float2(-st * cam,  st * sam);
    float2 U10 = make_float2( st * cam,  st * sam);
    float2 U11 = make_float2( ct * cap,  ct * sap);
    T00 = U00; T01 = U10; T10 = U01; T11 = U11;
}

// ---------------- Kernel A: data-independent prefix (layers 0..3) --------
// CNOT chain per layer is composed into ONE permutation sweep:
//   f_q(i) = (i & cb_q) ? i ^ tb_q : i, applied q=10..0 to the read index.
__global__ void k_psi0(const float* __restrict__ params) {
    __shared__ float2 st[DIM];
    int tid = threadIdx.x, nt = blockDim.x;  // nt = 1024
    for (int i = tid; i < DIM; i += nt)
        st[i] = make_float2(i == 0 ? 1.0f : 0.0f, 0.0f);
    __syncthreads();

    for (int l = 0; l < NLAYERS - 1; l++) {
        for (int q = 0; q < NQ; q++) {
            const float* p = params + (l * NQ + q) * 3;
            float2 T00, T01, T10, T11;
            make_UT(p[0], p[1], p[2], T00, T01, T10, T11);
            int mask = 1 << (NQ - 1 - q);
            for (int pi = tid; pi < DIM / 2; pi += nt) {
                int low = pi & (mask - 1);
                int hi  = (pi & ~(mask - 1)) << 1;
                int i0 = hi | low, i1 = i0 | mask;
                float2 s0 = st[i0], s1 = st[i1];
                st[i0] = cadd(cmul(T00, s0), cmul(T01, s1));
                st[i1] = cadd(cmul(T10, s0), cmul(T11, s1));
            }
            __syncthreads();
        }
        // composed CNOT permutation, single sweep (4 indices per thread)
        {
            float2 tmp[4];
#pragma unroll
            for (int u = 0; u < 4; u++) {
                int idx = u * 1024 + tid;
                int j = idx;
#pragma unroll
                for (int q = NQ - 2; q >= 0; q--) {
                    int cb = 1 << (NQ - 1 - q);
                    int tb = 1 << (NQ - 2 - q);
                    if (j & cb) j ^= tb;
                }
                tmp[u] = st[j];
            }
            __syncthreads();
#pragma unroll
            for (int u = 0; u < 4; u++)
                st[u * 1024 + tid] = tmp[u];
            __syncthreads();
        }
    }
    for (int i = tid; i < DIM; i += nt) g_psi0[i] = st[i];
}

// ---------------- Kernel B: per-sample layer-4 gates + bf16 split --------
__global__ void k_states(const float* __restrict__ X,
                         const float* __restrict__ params) {
    __shared__ float2 st[DIM];
    int i = blockIdx.x, tid = threadIdx.x, nt = blockDim.x;
    for (int k = tid; k < DIM; k += nt) st[k] = g_psi0[k];
    __syncthreads();

    for (int q = 0; q < NQ; q++) {
        const float* p = params + ((NLAYERS - 1) * NQ + q) * 3;
        float2 T00, T01, T10, T11;
        make_UT(p[0], p[1], p[2], T00, T01, T10, T11);
        float x = X[i * NQ + q];
        float gc = cosf(0.5f * x), gs = sinf(0.5f * x);
        // V = G^T * T
        float2 V00 = make_float2(gc * T00.x + gs * T10.x, gc * T00.y + gs * T10.y);
        float2 V01 = make_float2(gc * T01.x + gs * T11.x, gc * T01.y + gs * T11.y);
        float2 V10 = make_float2(-gs * T00.x + gc * T10.x, -gs * T00.y + gc * T10.y);
        float2 V11 = make_float2(-gs * T01.x + gc * T11.x, -gs * T01.y + gc * T11.y);

        int mask = 1 << (NQ - 1 - q);
        for (int pi = tid; pi < DIM / 2; pi += nt) {
            int low = pi & (mask - 1);
            int hi  = (pi & ~(mask - 1)) << 1;
            int i0 = hi | low, i1 = i0 | mask;
            float2 s0 = st[i0], s1 = st[i1];
            st[i0] = cadd(cmul(V00, s0), cmul(V01, s1));
            st[i1] = cadd(cmul(V10, s0), cmul(V11, s1));
        }
        __syncthreads();
    }

    size_t rowoff = (size_t)i * DIM;
    for (int k = tid; k < DIM; k += nt) {
        float re = st[k].x, im = st[k].y;
        __nv_bfloat16 hr = __float2bfloat16_rn(re);
        __nv_bfloat16 hi = __float2bfloat16_rn(im);
        __nv_bfloat16 lr = __float2bfloat16_rn(re - __bfloat162float(hr));
        __nv_bfloat16 li = __float2bfloat16_rn(im - __bfloat162float(hi));
        __nv_bfloat162 ah; ah.x = hr; ah.y = hi;
        __nv_bfloat162 al; al.x = lr; al.y = li;
        g_Ah[rowoff + k] = ah;
        g_Al[rowoff + k] = al;
    }
}

// =============  Kernel C: HMMA (mma.sync bf16) split Gram  ================
// re: Ah.Ah + Ah.Al + Al.Ah  (3 chains — needed for the diagonal)
// im: Ah.Ch only             (1 chain  — lo terms negligible for |g|^2)
//   Ch fragments derived in-register: (re,im) -> (-im,re).
// K_out = re^2 + im^2.  Triangular 128x128 tiles.
#define KELEMS    8192
#define KCHUNK    64                    // bf16 per chunk (128 bytes)
#define NKT       (KELEMS / KCHUNK)     // 128
#define TILE_B    16384                 // 128 rows x 128 bytes
#define STAGE_B   (4 * TILE_B)          // Ah_i, Al_i, Ah_j, Al_j = 64KB
#define NSTAGE    3
#define GRAM_SMEM (NSTAGE * STAGE_B)    // 192KB
#define GRAM_THREADS 256
#define NTILE (DIM / 128)               // 32
#define NBLK  (NTILE * (NTILE + 1) / 2) // 528

__device__ __forceinline__ uint32_t smem_u32(const void* p) {
    return (uint32_t)__cvta_generic_to_shared(p);
}
__device__ __forceinline__ void cp_async16(uint32_t dst, const void* src) {
    asm volatile("cp.async.cg.shared.global [%0], [%1], 16;" :: "r"(dst), "l"(src));
}
#define CP_COMMIT()  asm volatile("cp.async.commit_group;" ::: "memory")
#define CP_WAIT2()   asm volatile("cp.async.wait_group 2;" ::: "memory")
#define CP_WAIT0()   asm volatile("cp.async.wait_group 0;" ::: "memory")

__device__ __forceinline__ void ldsm4(uint32_t* r, uint32_t addr) {
    asm volatile("ldmatrix.sync.aligned.m8n8.x4.shared.b16 {%0,%1,%2,%3}, [%4];"
        : "=r"(r[0]), "=r"(r[1]), "=r"(r[2]), "=r"(r[3]) : "r"(addr));
}
__device__ __forceinline__ void mma_bf16(float* c, const uint32_t* a,
                                         uint32_t b0, uint32_t b1) {
    asm volatile(
        "mma.sync.aligned.m16n8k16.row.col.f32.bf16.bf16.f32 "
        "{%0,%1,%2,%3}, {%4,%5,%6,%7}, {%8,%9}, {%0,%1,%2,%3};"
        : "+f"(c[0]), "+f"(c[1]), "+f"(c[2]), "+f"(c[3])
        : "r"(a[0]), "r"(a[1]), "r"(a[2]), "r"(a[3]), "r"(b0), "r"(b1));
}
// (re,im) packed pair -> (-im, re)
__device__ __forceinline__ uint32_t derive_c(uint32_t b) {
    return __byte_perm(b, b, 0x1032) ^ 0x00008000u;
}

__global__ void __launch_bounds__(GRAM_THREADS, 1)
k_gram_mma(float* __restrict__ K) {
    extern __shared__ __align__(1024) char smem[];
    const uint32_t smem_base = smem_u32(smem);
    const int tid  = threadIdx.x;
    const int wid  = tid >> 5;
    const int lane = tid & 31;
    const int wm = wid >> 2;            // 0..1  (64-row slab)
    const int wn = wid & 3;             // 0..3  (32-col slab)

    // triangular tile mapping (bi <= bj)
    int t = blockIdx.x;
    int bj = (int)((sqrtf(8.0f * (float)t + 1.0f) - 1.0f) * 0.5f);
    while ((bj + 1) * (bj + 2) / 2 <= t) bj++;
    while (bj * (bj + 1) / 2 > t) bj--;
    int bi = t - bj * (bj + 1) / 2;

    const char* gsrc[4];
    gsrc[0] = (const char*)g_Ah + (size_t)bi * 128 * 16384;
    gsrc[1] = (const char*)g_Al + (size_t)bi * 128 * 16384;
    gsrc[2] = (const char*)g_Ah + (size_t)bj * 128 * 16384;
    gsrc[3] = (const char*)g_Al + (size_t)bj * 128 * 16384;

    // ldmatrix per-thread geometry
    const int mat = lane >> 3, rl = lane & 7;
    const int rowA_base = wm * 64 + (mat & 1) * 8 + rl;   // + mt*16
    const uint32_t kselA = (uint32_t)((mat >> 1) * 16);
    const uint32_t xA = (uint32_t)(rowA_base & 7) << 4;
    const int rowB_base = wn * 32 + (mat >> 1) * 8 + rl;  // + np*16
    const uint32_t kselB = (uint32_t)((mat & 1) * 16);
    const uint32_t xB = (uint32_t)(rowB_base & 7) << 4;

    float acc[2][4][4][4];
#pragma unroll
    for (int e = 0; e < 2; e++)
#pragma unroll
        for (int mt = 0; mt < 4; mt++)
#pragma unroll
            for (int nt = 0; nt < 4; nt++)
#pragma unroll
                for (int r = 0; r < 4; r++) acc[e][mt][nt][r] = 0.f;

    // ---------------- prologue: fill 3 stages --------------------------
#pragma unroll 1
    for (int pk = 0; pk < NSTAGE; pk++) {
        uint32_t sb = smem_base + pk * STAGE_B;
#pragma unroll
        for (int tt = 0; tt < 4; tt++) {
#pragma unroll
            for (int u = 0; u < 4; u++) {
                int p = u * 256 + tid;
                int rr = p >> 3, cc = p & 7;
                uint32_t dst = sb + tt * TILE_B + (uint32_t)rr * 128 +
                               (((uint32_t)cc * 16) ^ (((uint32_t)rr & 7) << 4));
                cp_async16(dst, gsrc[tt] + (size_t)rr * 16384 + pk * 128 + cc * 16);
            }
        }
        CP_COMMIT();
    }

    // ---------------- main loop ----------------------------------------
#pragma unroll 1
    for (int kt = 0; kt < NKT; kt++) {
        CP_WAIT2();
        __syncthreads();

        uint32_t sb = smem_base + (kt % NSTAGE) * STAGE_B;
        uint32_t aH = sb + (uint32_t)rowA_base * 128;
        uint32_t aL = aH + TILE_B;
        uint32_t bH = sb + 2 * TILE_B + (uint32_t)rowB_base * 128;
        uint32_t bL = bH + TILE_B;

#pragma unroll
        for (int ks = 0; ks < 4; ks++) {
            uint32_t cA = ((uint32_t)(ks * 32) + kselA) ^ xA;
            uint32_t cB = ((uint32_t)(ks * 32) + kselB) ^ xB;

            uint32_t ah[4][4], al[4][4];
#pragma unroll
            for (int mt = 0; mt < 4; mt++) {
                ldsm4(ah[mt], aH + mt * 2048 + cA);
                ldsm4(al[mt], aL + mt * 2048 + cA);
            }
            uint32_t bh[2][4], bl[2][4], bhp[2][4];
#pragma unroll
            for (int np = 0; np < 2; np++) {
                ldsm4(bh[np], bH + np * 2048 + cB);
                ldsm4(bl[np], bL + np * 2048 + cB);
#pragma unroll
                for (int r = 0; r < 4; r++)
                    bhp[np][r] = derive_c(bh[np][r]);
            }

            // chain-ordered: consecutive MMAs always hit distinct accs
#pragma unroll
            for (int mt = 0; mt < 4; mt++)          // re: Ah.Ah
#pragma unroll
                for (int np = 0; np < 2; np++)
#pragma unroll
                    for (int h = 0; h < 2; h++)
                        mma_bf16(acc[0][mt][np * 2 + h], ah[mt],
                                 bh[np][h * 2], bh[np][h * 2 + 1]);
#pragma unroll
            for (int mt = 0; mt < 4; mt++)          // re: Ah.Al
#pragma unroll
                for (int np = 0; np < 2; np++)
#pragma unroll
                    for (int h = 0; h < 2; h++)
                        mma_bf16(acc[0][mt][np * 2 + h], ah[mt],
                                 bl[np][h * 2], bl[np][h * 2 + 1]);
#pragma unroll
            for (int mt = 0; mt < 4; mt++)          // re: Al.Ah
#pragma unroll
                for (int np = 0; np < 2; np++)
#pragma unroll
                    for (int h = 0; h < 2; h++)
                        mma_bf16(acc[0][mt][np * 2 + h], al[mt],
                                 bh[np][h * 2], bh[np][h * 2 + 1]);
#pragma unroll
            for (int mt = 0; mt < 4; mt++)          // im: Ah.Ch
#pragma unroll
                for (int np = 0; np < 2; np++)
#pragma unroll
                    for (int h = 0; h < 2; h++)
                        mma_bf16(acc[1][mt][np * 2 + h], ah[mt],
                                 bhp[np][h * 2], bhp[np][h * 2 + 1]);
        }

        __syncthreads();

        int nk = kt + NSTAGE;
        if (nk < NKT) {
#pragma unroll
            for (int tt = 0; tt < 4; tt++) {
#pragma unroll
                for (int u = 0; u < 4; u++) {
                    int p = u * 256 + tid;
                    int rr = p >> 3, cc = p & 7;
                    uint32_t dst = sb + tt * TILE_B + (uint32_t)rr * 128 +
                                   (((uint32_t)cc * 16) ^ (((uint32_t)rr & 7) << 4));
                    cp_async16(dst, gsrc[tt] + (size_t)rr * 16384 + nk * 128 + cc * 16);
                }
            }
        }
        CP_COMMIT();
    }

    // ---------------- epilogue: K = re^2 + im^2 ------------------------
    CP_WAIT0();
    __syncthreads();                      // smem tiles dead; reuse for transpose

    float* T = (float*)smem;              // [128 cols][132 pitch] local transpose
    const int r0 = bi * 128 + wm * 64 + (lane >> 2);
    const int c0 = bj * 128 + wn * 32 + (lane & 3) * 2;
    const int rl0 = wm * 64 + (lane >> 2);
    const int cl0 = wn * 32 + (lane & 3) * 2;
#pragma unroll
    for (int mt = 0; mt < 4; mt++) {
#pragma unroll
        for (int nt = 0; nt < 4; nt++) {
            int row = r0 + mt * 16;
            int col = c0 + nt * 8;
            float* re = acc[0][mt][nt];
            float* im = acc[1][mt][nt];
            float v00 = re[0] * re[0] + im[0] * im[0];
            float v01 = re[1] * re[1] + im[1] * im[1];
            float v10 = re[2] * re[2] + im[2] * im[2];
            float v11 = re[3] * re[3] + im[3] * im[3];
            *(float2*)(K + (size_t)row * BSZ + col)       = make_float2(v00, v01);
            *(float2*)(K + (size_t)(row + 8) * BSZ + col) = make_float2(v10, v11);
            if (bi != bj) {
                int rr = rl0 + mt * 16, cc = cl0 + nt * 8;
                T[cc * 132 + rr]           = v00;
                T[(cc + 1) * 132 + rr]     = v01;
                T[cc * 132 + rr + 8]       = v10;
                T[(cc + 1) * 132 + rr + 8] = v11;
            }
        }
    }
    __syncthreads();
    if (bi != bj) {
        // coalesced mirror: row c of T -> K[(bj*128+c)][bi*128 ..]
        int c = tid >> 1, half = tid & 1;
        float4* dst = (float4*)(K + (size_t)(bj * 128 + c) * BSZ + bi * 128 + half * 64);
        const float* src = T + c * 132 + half * 64;
#pragma unroll
        for (int i = 0; i < 16; i++)
            dst[i] = make_float4(src[4 * i], src[4 * i + 1],
                                 src[4 * i + 2], src[4 * i + 3]);
    }
}

// -------------------------------------------------------------------------
extern "C" void kernel_launch(void* const* d_in, const int* in_sizes, int n_in,
                              void* d_out, int out_size) {
    const float* X      = (const float*)d_in[0];   // (4096, 12)
    const float* params = (const float*)d_in[1];   // (5, 12, 3)
    float* K = (float*)d_out;                      // (4096, 4096)

    cudaFuncSetAttribute(k_gram_mma, cudaFuncAttributeMaxDynamicSharedMemorySize,
                         GRAM_SMEM);

    k_psi0    <<<1,    1024>>>(params);
    k_states  <<<BSZ,  256>>>(X, params);
    k_gram_mma<<<NBLK, GRAM_THREADS, GRAM_SMEM>>>(K);
}